// round 2
// baseline (speedup 1.0000x reference)
#include <cuda_runtime.h>
#include <cuda_bf16.h>
#include <cstdint>

#define MDIM 10000
#define NDIM 512
#define KDIM 512
#define MAXE 204800

// ---------------- device scratch (static; no allocation) --------------------
__device__ float          g_ZW[(size_t)MDIM * NDIM];   // Z @ W, fp32
__device__ __nv_bfloat16  g_Zhi[(size_t)MDIM * KDIM];
__device__ __nv_bfloat16  g_Zlo[(size_t)MDIM * KDIM];
__device__ __nv_bfloat16  g_Whi[(size_t)KDIM * NDIM];
__device__ __nv_bfloat16  g_Wlo[(size_t)KDIM * NDIM];
__device__ int g_idx64;
__device__ int g_hist[MDIM];
__device__ int g_off[MDIM];
__device__ int g_sr[MAXE];   // sorted-by-c: row index
__device__ int g_sc[MAXE];   // sorted-by-c: col index
__device__ int g_si[MAXE];   // sorted-by-c: original edge index

// ---------------------------------------------------------------------------
// Convert Z and W into bf16 hi/lo splits, zero the histogram, and detect the
// edge-index dtype (int64 <=> all odd 32-bit words of the first 128 entries
// are zero, since indices < 10000).
// ---------------------------------------------------------------------------
__global__ void convert_kernel(const float* __restrict__ Z,
                               const float* __restrict__ W,
                               const unsigned int* __restrict__ e32) {
    const long long nZ4 = (long long)MDIM * KDIM / 4;
    const long long nW4 = (long long)KDIM * NDIM / 4;
    long long i4 = (long long)blockIdx.x * blockDim.x + threadIdx.x;

    if (i4 < nZ4) {
        float4 v = ((const float4*)Z)[i4];
        __nv_bfloat16 h0 = __float2bfloat16(v.x);
        __nv_bfloat16 h1 = __float2bfloat16(v.y);
        __nv_bfloat16 h2 = __float2bfloat16(v.z);
        __nv_bfloat16 h3 = __float2bfloat16(v.w);
        __nv_bfloat162* hi = (__nv_bfloat162*)(g_Zhi + i4 * 4);
        __nv_bfloat162* lo = (__nv_bfloat162*)(g_Zlo + i4 * 4);
        hi[0] = __nv_bfloat162(h0, h1);
        hi[1] = __nv_bfloat162(h2, h3);
        lo[0] = __nv_bfloat162(__float2bfloat16(v.x - __bfloat162float(h0)),
                               __float2bfloat16(v.y - __bfloat162float(h1)));
        lo[1] = __nv_bfloat162(__float2bfloat16(v.z - __bfloat162float(h2)),
                               __float2bfloat16(v.w - __bfloat162float(h3)));
    } else if (i4 < nZ4 + nW4) {
        long long j4 = i4 - nZ4;
        float4 v = ((const float4*)W)[j4];
        __nv_bfloat16 h0 = __float2bfloat16(v.x);
        __nv_bfloat16 h1 = __float2bfloat16(v.y);
        __nv_bfloat16 h2 = __float2bfloat16(v.z);
        __nv_bfloat16 h3 = __float2bfloat16(v.w);
        __nv_bfloat162* hi = (__nv_bfloat162*)(g_Whi + j4 * 4);
        __nv_bfloat162* lo = (__nv_bfloat162*)(g_Wlo + j4 * 4);
        hi[0] = __nv_bfloat162(h0, h1);
        hi[1] = __nv_bfloat162(h2, h3);
        lo[0] = __nv_bfloat162(__float2bfloat16(v.x - __bfloat162float(h0)),
                               __float2bfloat16(v.y - __bfloat162float(h1)));
        lo[1] = __nv_bfloat162(__float2bfloat16(v.z - __bfloat162float(h2)),
                               __float2bfloat16(v.w - __bfloat162float(h3)));
    }

    long long t = (long long)blockIdx.x * blockDim.x + threadIdx.x;
    if (t < MDIM) g_hist[t] = 0;

    if (blockIdx.x == 0 && threadIdx.x < 32) {
        int bad = 0;
        for (int i = (int)threadIdx.x; i < 128; i += 32)
            if (e32[2 * i + 1] != 0u) bad = 1;
        unsigned m = __ballot_sync(0xFFFFFFFFu, bad);
        if (threadIdx.x == 0) g_idx64 = (m == 0u);
    }
}

// ---------------------------------------------------------------------------
// ZW = Z @ W with fp32-equivalent precision via split-bf16 tensor cores:
//   ZW ~= Zhi*Whi + Zhi*Wlo + Zlo*Whi      (lo*lo term ~2^-18, dropped)
// mma.sync.aligned.m16n8k16.row.col.f32.bf16.bf16.f32
// Block: 256 thr (8 warps as 2x4), tile BM=64 x BN=128 x BK=32, warp 32x32.
// ---------------------------------------------------------------------------
__device__ __forceinline__ void mma_bf16(float* c, const uint32_t* a, const uint32_t* b) {
    asm volatile(
        "mma.sync.aligned.m16n8k16.row.col.f32.bf16.bf16.f32 "
        "{%0,%1,%2,%3}, {%4,%5,%6,%7}, {%8,%9}, {%0,%1,%2,%3};"
        : "+f"(c[0]), "+f"(c[1]), "+f"(c[2]), "+f"(c[3])
        : "r"(a[0]), "r"(a[1]), "r"(a[2]), "r"(a[3]), "r"(b[0]), "r"(b[1]));
}

#define GBM 64
#define GBN 128
#define GBK 32

__global__ __launch_bounds__(256)
void gemm_bf16split_kernel() {
    __shared__ __nv_bfloat16 As_hi[GBM][GBK];
    __shared__ __nv_bfloat16 As_lo[GBM][GBK];
    __shared__ __nv_bfloat16 Bs_hi[GBN][GBK];   // stored transposed: [n][k]
    __shared__ __nv_bfloat16 Bs_lo[GBN][GBK];

    const int bm = blockIdx.y * GBM;
    const int bn = blockIdx.x * GBN;
    const int tid = (int)threadIdx.x;
    const int wid = tid >> 5;
    const int lane = tid & 31;
    const int wm = (wid & 1) * 32;     // warp m offset in block tile
    const int wn = (wid >> 1) * 32;    // warp n offset in block tile
    const int g = lane >> 2;           // groupID
    const int tg = lane & 3;           // thread-in-group

    float acc[2][4][4];
#pragma unroll
    for (int mi = 0; mi < 2; mi++)
#pragma unroll
        for (int ni = 0; ni < 4; ni++)
#pragma unroll
            for (int j = 0; j < 4; j++) acc[mi][ni][j] = 0.0f;

    for (int k0 = 0; k0 < KDIM; k0 += GBK) {
        // A tile: 64x32, 8 elems/thread
#pragma unroll
        for (int i = 0; i < 8; i++) {
            int flat = tid + 256 * i;
            int r = flat >> 5, k = flat & 31;
            int grow = bm + r;
            __nv_bfloat16 hi = __float2bfloat16(0.0f), lo = hi;
            if (grow < MDIM) {
                size_t gi = (size_t)grow * KDIM + k0 + k;
                hi = g_Zhi[gi]; lo = g_Zlo[gi];
            }
            As_hi[r][k] = hi;
            As_lo[r][k] = lo;
        }
        // B tile: 32x128 -> transposed smem [n][k], 16 elems/thread
#pragma unroll
        for (int i = 0; i < 16; i++) {
            int flat = tid + 256 * i;
            int k = flat >> 7, n = flat & 127;
            size_t gi = (size_t)(k0 + k) * NDIM + bn + n;
            Bs_hi[n][k] = g_Whi[gi];
            Bs_lo[n][k] = g_Wlo[gi];
        }
        __syncthreads();

#pragma unroll
        for (int kk = 0; kk < GBK; kk += 16) {
            uint32_t ahi[2][4], alo[2][4], bhi[4][2], blo[4][2];
#pragma unroll
            for (int mi = 0; mi < 2; mi++) {
                int r0 = wm + mi * 16 + g;
                int kc = kk + tg * 2;
                ahi[mi][0] = *(const uint32_t*)&As_hi[r0][kc];
                ahi[mi][1] = *(const uint32_t*)&As_hi[r0 + 8][kc];
                ahi[mi][2] = *(const uint32_t*)&As_hi[r0][kc + 8];
                ahi[mi][3] = *(const uint32_t*)&As_hi[r0 + 8][kc + 8];
                alo[mi][0] = *(const uint32_t*)&As_lo[r0][kc];
                alo[mi][1] = *(const uint32_t*)&As_lo[r0 + 8][kc];
                alo[mi][2] = *(const uint32_t*)&As_lo[r0][kc + 8];
                alo[mi][3] = *(const uint32_t*)&As_lo[r0 + 8][kc + 8];
            }
#pragma unroll
            for (int ni = 0; ni < 4; ni++) {
                int n0 = wn + ni * 8 + g;
                int kc = kk + tg * 2;
                bhi[ni][0] = *(const uint32_t*)&Bs_hi[n0][kc];
                bhi[ni][1] = *(const uint32_t*)&Bs_hi[n0][kc + 8];
                blo[ni][0] = *(const uint32_t*)&Bs_lo[n0][kc];
                blo[ni][1] = *(const uint32_t*)&Bs_lo[n0][kc + 8];
            }
#pragma unroll
            for (int mi = 0; mi < 2; mi++)
#pragma unroll
                for (int ni = 0; ni < 4; ni++) {
                    mma_bf16(acc[mi][ni], ahi[mi], bhi[ni]);
                    mma_bf16(acc[mi][ni], ahi[mi], blo[ni]);
                    mma_bf16(acc[mi][ni], alo[mi], bhi[ni]);
                }
        }
        __syncthreads();
    }

    // Epilogue: c0,c1 -> (row, col..col+1); c2,c3 -> (row+8, col..col+1)
#pragma unroll
    for (int mi = 0; mi < 2; mi++)
#pragma unroll
        for (int ni = 0; ni < 4; ni++) {
            int row = bm + wm + mi * 16 + g;
            int col = bn + wn + ni * 8 + tg * 2;
            if (row < MDIM) {
                float2 v = make_float2(acc[mi][ni][0], acc[mi][ni][1]);
                *(float2*)&g_ZW[(size_t)row * NDIM + col] = v;
            }
            if (row + 8 < MDIM) {
                float2 v = make_float2(acc[mi][ni][2], acc[mi][ni][3]);
                *(float2*)&g_ZW[(size_t)(row + 8) * NDIM + col] = v;
            }
        }
}

// ---------------------------------------------------------------------------
// Counting sort of edges by column node c.
// ---------------------------------------------------------------------------
__device__ __forceinline__ void load_edge(const void* edges, int E, int e,
                                          int& r, int& c) {
    if (g_idx64) {
        const long long* p = (const long long*)edges;
        r = (int)p[e];
        c = (int)p[(size_t)E + e];
    } else {
        const int* p = (const int*)edges;
        r = p[e];
        c = p[(size_t)E + e];
    }
}

__global__ void hist_kernel(const void* __restrict__ edges, int E) {
    int e = blockIdx.x * blockDim.x + threadIdx.x;
    if (e >= E) return;
    int r, c;
    load_edge(edges, E, e, r, c);
    atomicAdd(&g_hist[c], 1);
}

__global__ __launch_bounds__(1024)
void scan_kernel() {
    __shared__ int sh[1024];
    const int t = (int)threadIdx.x;
    const int base = t * 10;
    int s = 0;
#pragma unroll
    for (int j = 0; j < 10; j++) {
        int idx = base + j;
        if (idx < MDIM) s += g_hist[idx];
    }
    sh[t] = s;
    __syncthreads();
    for (int off = 1; off < 1024; off <<= 1) {
        int v = (t >= off) ? sh[t - off] : 0;
        __syncthreads();
        sh[t] += v;
        __syncthreads();
    }
    int run = sh[t] - s;   // exclusive
#pragma unroll
    for (int j = 0; j < 10; j++) {
        int idx = base + j;
        if (idx < MDIM) {
            g_off[idx] = run;
            run += g_hist[idx];
        }
    }
}

__global__ void scatter_kernel(const void* __restrict__ edges, int E) {
    int e = blockIdx.x * blockDim.x + threadIdx.x;
    if (e >= E) return;
    int r, c;
    load_edge(edges, E, e, r, c);
    int pos = atomicAdd(&g_off[c], 1);
    g_sr[pos] = r;
    g_sc[pos] = c;
    g_si[pos] = e;
}

// ---------------------------------------------------------------------------
// Per-edge score on c-sorted edges: one warp per edge.
// Z[c] is shared by ~16 warps per block (same/nearby c) -> L1-resident.
// ---------------------------------------------------------------------------
__global__ __launch_bounds__(512)
void edge_kernel(const float* __restrict__ Z, float* __restrict__ out, int E) {
    int w = (int)((blockIdx.x * 512u + threadIdx.x) >> 5);
    int lane = (int)(threadIdx.x & 31);
    if (w >= E) return;
    int r = g_sr[w], c = g_sc[w];

    const float4* a = (const float4*)(g_ZW + (size_t)r * NDIM);
    const float4* b = (const float4*)(Z + (size_t)c * NDIM);
    float sum = 0.0f;
#pragma unroll
    for (int i = 0; i < 4; i++) {
        float4 x = a[lane + 32 * i];
        float4 y = b[lane + 32 * i];
        sum = fmaf(x.x, y.x, fmaf(x.y, y.y, fmaf(x.z, y.z, fmaf(x.w, y.w, sum))));
    }
#pragma unroll
    for (int o = 16; o; o >>= 1)
        sum += __shfl_xor_sync(0xFFFFFFFFu, sum, o);
    if (lane == 0)
        out[g_si[w]] = 1.0f / (1.0f + expf(-sum));
}

// Fallback (unsorted, direct) in case E exceeds the static sort buffers.
__global__ __launch_bounds__(512)
void edge_direct_kernel(const float* __restrict__ Z,
                        const void* __restrict__ edges,
                        float* __restrict__ out, int E) {
    int w = (int)((blockIdx.x * 512u + threadIdx.x) >> 5);
    int lane = (int)(threadIdx.x & 31);
    if (w >= E) return;
    int r, c;
    load_edge(edges, E, w, r, c);
    const float4* a = (const float4*)(g_ZW + (size_t)r * NDIM);
    const float4* b = (const float4*)(Z + (size_t)c * NDIM);
    float sum = 0.0f;
#pragma unroll
    for (int i = 0; i < 4; i++) {
        float4 x = a[lane + 32 * i];
        float4 y = b[lane + 32 * i];
        sum = fmaf(x.x, y.x, fmaf(x.y, y.y, fmaf(x.z, y.z, fmaf(x.w, y.w, sum))));
    }
#pragma unroll
    for (int o = 16; o; o >>= 1)
        sum += __shfl_xor_sync(0xFFFFFFFFu, sum, o);
    if (lane == 0)
        out[w] = 1.0f / (1.0f + expf(-sum));
}

// ---------------------------------------------------------------------------
extern "C" void kernel_launch(void* const* d_in, const int* in_sizes, int n_in,
                              void* d_out, int out_size) {
    const float* z_drug = (const float*)d_in[0];   // [10000, 512] f32
    const float* weight = (const float*)d_in[1];   // [512, 512]   f32
    const void*  edges  = d_in[2];                 // [2, E] int64 or int32
    float* out = (float*)d_out;
    const int E = out_size;

    // 1. convert + hist-zero + dtype detect
    long long total4 = ((long long)MDIM * KDIM + (long long)KDIM * NDIM) / 4;
    int cblocks = (int)((total4 + 255) / 256);
    convert_kernel<<<cblocks, 256>>>(z_drug, weight, (const unsigned int*)edges);

    // 2. ZW = Z @ W (split-bf16 tensor cores)
    dim3 ggrid(NDIM / GBN, (MDIM + GBM - 1) / GBM);   // (4, 157)
    gemm_bf16split_kernel<<<ggrid, 256>>>();

    if (E <= MAXE) {
        // 3. counting sort by c
        int eblocks = (E + 255) / 256;
        hist_kernel<<<eblocks, 256>>>(edges, E);
        scan_kernel<<<1, 1024>>>();
        scatter_kernel<<<eblocks, 256>>>(edges, E);
        // 4. scores
        int sblocks = (E + 15) / 16;   // 16 warps (edges) per 512-thr block
        edge_kernel<<<sblocks, 512>>>(z_drug, out, E);
    } else {
        int sblocks = (E + 15) / 16;
        edge_direct_kernel<<<sblocks, 512>>>(z_drug, edges, out, E);
    }
}

// round 3
// speedup vs baseline: 2.9189x; 2.9189x over previous
#include <cuda_runtime.h>
#include <cuda_bf16.h>
#include <cstdint>

#define MDIM 10000
#define NDIM 512
#define KDIM 512
#define AST  40     // smem tile row stride in bf16 (32 + 8 pad: conflict-free ldmatrix)

// ---------------- device scratch (static; no allocation) --------------------
__device__ float         g_ZW[(size_t)MDIM * NDIM];    // Z @ W, fp32
__device__ __nv_bfloat16 g_WThi[(size_t)NDIM * KDIM];  // W^T, bf16 hi split  [n][k]
__device__ __nv_bfloat16 g_WTlo[(size_t)NDIM * KDIM];  // W^T, bf16 lo split  [n][k]
__device__ int g_idx64;

// ---------------------------------------------------------------------------
__device__ __forceinline__ void mma_bf16(float* c, const uint32_t* a, const uint32_t* b) {
    asm volatile(
        "mma.sync.aligned.m16n8k16.row.col.f32.bf16.bf16.f32 "
        "{%0,%1,%2,%3}, {%4,%5,%6,%7}, {%8,%9}, {%0,%1,%2,%3};"
        : "+f"(c[0]), "+f"(c[1]), "+f"(c[2]), "+f"(c[3])
        : "r"(a[0]), "r"(a[1]), "r"(a[2]), "r"(a[3]), "r"(b[0]), "r"(b[1]));
}

__device__ __forceinline__ void ldsm_x4(uint32_t* r, uint32_t addr) {
    asm volatile("ldmatrix.sync.aligned.m8n8.x4.shared.b16 {%0,%1,%2,%3}, [%4];"
                 : "=r"(r[0]), "=r"(r[1]), "=r"(r[2]), "=r"(r[3]) : "r"(addr));
}

// ---------------------------------------------------------------------------
// Transpose W (512x512 f32, [k][n]) into bf16 hi/lo splits [n][k], and detect
// the edge-index dtype (int64 <=> all odd 32-bit words of the first 128
// entries are zero, since indices < 10000; P(false positive) ~ 1e-512).
// ---------------------------------------------------------------------------
__global__ void wt_convert_kernel(const float* __restrict__ W,
                                  const unsigned int* __restrict__ e32) {
    __shared__ float t[32][33];
    const int bx = blockIdx.x, by = blockIdx.y;
    const int tx = (int)threadIdx.x, ty = (int)threadIdx.y;   // 32 x 8

#pragma unroll
    for (int j = 0; j < 4; j++)
        t[ty + j * 8][tx] = W[(size_t)(by * 32 + ty + j * 8) * NDIM + bx * 32 + tx];
    __syncthreads();

#pragma unroll
    for (int j = 0; j < 4; j++) {
        int n = bx * 32 + ty + j * 8;
        int k = by * 32 + tx;
        float v = t[tx][ty + j * 8];
        __nv_bfloat16 h = __float2bfloat16(v);
        g_WThi[(size_t)n * KDIM + k] = h;
        g_WTlo[(size_t)n * KDIM + k] = __float2bfloat16(v - __bfloat162float(h));
    }

    if (bx == 0 && by == 0 && ty == 0) {
        int bad = 0;
        for (int i = tx; i < 128; i += 32)
            if (e32[2 * i + 1] != 0u) bad = 1;
        unsigned m = __ballot_sync(0xFFFFFFFFu, bad);
        if (tx == 0) g_idx64 = (m == 0u);
    }
}

// ---------------------------------------------------------------------------
// ZW = Z @ W with fp32-equivalent precision via split-bf16 tensor cores:
//   ZW ~= Zhi*Whi + Zhi*Wlo + Zlo*Whi          (lo*lo ~2^-18 rel, dropped)
// Block tile 128x128x32, 8 warps (2x4), warp tile 64x32.
// Z is converted fp32 -> (hi,lo) bf16 inline during the smem store.
// Register-staged pipeline: LDG for tile i+1 overlaps MMA on tile i.
// ---------------------------------------------------------------------------
__global__ __launch_bounds__(256)
void gemm_kernel(const float* __restrict__ Z) {
    __shared__ __nv_bfloat16 As_hi[128 * AST];
    __shared__ __nv_bfloat16 As_lo[128 * AST];
    __shared__ __nv_bfloat16 Bs_hi[128 * AST];
    __shared__ __nv_bfloat16 Bs_lo[128 * AST];

    const int bm = blockIdx.y * 128;
    const int bn = blockIdx.x * 128;
    const int tid = (int)threadIdx.x;
    const int lane = tid & 31, wid = tid >> 5;
    const int wm = (wid & 1) * 64;      // warp m offset
    const int wn = (wid >> 1) * 32;     // warp n offset
    const int g = lane >> 2, tg = lane & 3;

    const uint32_t s_ahi = (uint32_t)__cvta_generic_to_shared(As_hi);
    const uint32_t s_alo = (uint32_t)__cvta_generic_to_shared(As_lo);
    const uint32_t s_bhi = (uint32_t)__cvta_generic_to_shared(Bs_hi);
    const uint32_t s_blo = (uint32_t)__cvta_generic_to_shared(Bs_lo);

    // ldmatrix lane addressing.
    // A (m-major, [m][k]): per m16 tile: lanes 0-15 -> rows, k+0; 16-31 -> rows, k+8.
    uint32_t aoff[4];
#pragma unroll
    for (int mi = 0; mi < 4; mi++)
        aoff[mi] = (uint32_t)(((wm + mi * 16 + (lane & 15)) * AST + (lane >> 4) * 8) * 2);
    // B (n-major, [n][k]): x4 over two n8 tiles:
    //   lanes 0-7: n0+l,k0 | 8-15: n0+l,k8 | 16-23: n0+8+l,k0 | 24-31: n0+8+l,k8
    uint32_t boff[2];
    {
        int q = lane >> 3, l8 = lane & 7;
        int n_l = (q >> 1) * 8 + l8;
        int k_l = (q & 1) * 8;
#pragma unroll
        for (int nc = 0; nc < 2; nc++)
            boff[nc] = (uint32_t)(((wn + nc * 16 + n_l) * AST + k_l) * 2);
    }

    float acc[4][4][4];
#pragma unroll
    for (int mi = 0; mi < 4; mi++)
#pragma unroll
        for (int ni = 0; ni < 4; ni++)
#pragma unroll
            for (int j = 0; j < 4; j++) acc[mi][ni][j] = 0.0f;

    float4 areg[4];
    uint4  bhreg[2], blreg[2];

    auto ldg = [&](int k0) {
#pragma unroll
        for (int i = 0; i < 4; i++) {                 // A: 128x32 f32, 4 float4/thr
            int flat = tid + 256 * i;
            int row = flat >> 3, c4 = (flat & 7) * 4;
            int grow = bm + row;
            areg[i] = (grow < MDIM)
                ? *(const float4*)(Z + (size_t)grow * KDIM + k0 + c4)
                : make_float4(0.f, 0.f, 0.f, 0.f);
        }
#pragma unroll
        for (int i = 0; i < 2; i++) {                 // B: 128x32 bf16 x2, uint4 loads
            int flat = tid + 256 * i;
            int row = flat >> 2, c8 = (flat & 3) * 8;
            size_t gi = (size_t)(bn + row) * KDIM + k0 + c8;
            bhreg[i] = *(const uint4*)(g_WThi + gi);
            blreg[i] = *(const uint4*)(g_WTlo + gi);
        }
    };

    auto sts = [&]() {
#pragma unroll
        for (int i = 0; i < 4; i++) {
            int flat = tid + 256 * i;
            int row = flat >> 3, c4 = (flat & 7) * 4;
            float4 v = areg[i];
            __nv_bfloat16 h0 = __float2bfloat16(v.x);
            __nv_bfloat16 h1 = __float2bfloat16(v.y);
            __nv_bfloat16 h2 = __float2bfloat16(v.z);
            __nv_bfloat16 h3 = __float2bfloat16(v.w);
            __nv_bfloat162* ph = (__nv_bfloat162*)&As_hi[row * AST + c4];
            ph[0] = __nv_bfloat162(h0, h1);
            ph[1] = __nv_bfloat162(h2, h3);
            __nv_bfloat162* pl = (__nv_bfloat162*)&As_lo[row * AST + c4];
            pl[0] = __nv_bfloat162(__float2bfloat16(v.x - __bfloat162float(h0)),
                                   __float2bfloat16(v.y - __bfloat162float(h1)));
            pl[1] = __nv_bfloat162(__float2bfloat16(v.z - __bfloat162float(h2)),
                                   __float2bfloat16(v.w - __bfloat162float(h3)));
        }
#pragma unroll
        for (int i = 0; i < 2; i++) {
            int flat = tid + 256 * i;
            int row = flat >> 2, c8 = (flat & 3) * 8;
            *(uint4*)&Bs_hi[row * AST + c8] = bhreg[i];
            *(uint4*)&Bs_lo[row * AST + c8] = blreg[i];
        }
    };

    ldg(0);
    sts();
    __syncthreads();

    const int NIT = KDIM / 32;
    for (int it = 0; it < NIT; it++) {
        if (it + 1 < NIT) ldg((it + 1) * 32);    // LDG in flight during MMAs

#pragma unroll
        for (int kk = 0; kk < 32; kk += 16) {
            uint32_t Ahi[4][4], Alo[4][4], Bhi[2][4], Blo[2][4];
#pragma unroll
            for (int mi = 0; mi < 4; mi++) {
                ldsm_x4(Ahi[mi], s_ahi + aoff[mi] + kk * 2);
                ldsm_x4(Alo[mi], s_alo + aoff[mi] + kk * 2);
            }
#pragma unroll
            for (int nc = 0; nc < 2; nc++) {
                ldsm_x4(Bhi[nc], s_bhi + boff[nc] + kk * 2);
                ldsm_x4(Blo[nc], s_blo + boff[nc] + kk * 2);
            }
#pragma unroll
            for (int mi = 0; mi < 4; mi++)
#pragma unroll
                for (int ni = 0; ni < 4; ni++) {
                    const uint32_t* bh = &Bhi[ni >> 1][(ni & 1) * 2];
                    const uint32_t* bl = &Blo[ni >> 1][(ni & 1) * 2];
                    mma_bf16(acc[mi][ni], Ahi[mi], bh);
                    mma_bf16(acc[mi][ni], Ahi[mi], bl);
                    mma_bf16(acc[mi][ni], Alo[mi], bh);
                }
        }
        __syncthreads();
        if (it + 1 < NIT) { sts(); __syncthreads(); }
    }

    // Epilogue: c0,c1 -> (row, col..col+1); c2,c3 -> (row+8, ...)
#pragma unroll
    for (int mi = 0; mi < 4; mi++)
#pragma unroll
        for (int ni = 0; ni < 4; ni++) {
            int row = bm + wm + mi * 16 + g;
            int col = bn + wn + ni * 8 + tg * 2;
            if (row < MDIM)
                *(float2*)&g_ZW[(size_t)row * NDIM + col] =
                    make_float2(acc[mi][ni][0], acc[mi][ni][1]);
            if (row + 8 < MDIM)
                *(float2*)&g_ZW[(size_t)(row + 8) * NDIM + col] =
                    make_float2(acc[mi][ni][2], acc[mi][ni][3]);
        }
}

// ---------------------------------------------------------------------------
// Per-edge score: one warp per edge.  score = dot(ZW[r], Z[c]); sigmoid.
// Both tables (20 MB each) are L2-resident -> runs at L2 bandwidth.
// ---------------------------------------------------------------------------
__device__ __forceinline__ void load_edge(const void* edges, int E, int e,
                                          int& r, int& c) {
    if (g_idx64) {
        const long long* p = (const long long*)edges;
        r = (int)p[e];
        c = (int)p[(size_t)E + e];
    } else {
        const int* p = (const int*)edges;
        r = p[e];
        c = p[(size_t)E + e];
    }
}

__global__ __launch_bounds__(256)
void edge_kernel(const float* __restrict__ Z,
                 const void* __restrict__ edges,
                 float* __restrict__ out, int E) {
    int w = (int)((blockIdx.x * 256u + threadIdx.x) >> 5);
    int lane = (int)(threadIdx.x & 31);
    if (w >= E) return;
    int r, c;
    load_edge(edges, E, w, r, c);

    const float4* a = (const float4*)(g_ZW + (size_t)r * NDIM);
    const float4* b = (const float4*)(Z + (size_t)c * NDIM);
    float sum = 0.0f;
#pragma unroll
    for (int i = 0; i < 4; i++) {
        float4 x = a[lane + 32 * i];
        float4 y = b[lane + 32 * i];
        sum = fmaf(x.x, y.x, fmaf(x.y, y.y, fmaf(x.z, y.z, fmaf(x.w, y.w, sum))));
    }
#pragma unroll
    for (int o = 16; o; o >>= 1)
        sum += __shfl_xor_sync(0xFFFFFFFFu, sum, o);
    if (lane == 0)
        out[w] = 1.0f / (1.0f + expf(-sum));
}

// ---------------------------------------------------------------------------
extern "C" void kernel_launch(void* const* d_in, const int* in_sizes, int n_in,
                              void* d_out, int out_size) {
    const float* z_drug = (const float*)d_in[0];   // [10000, 512] f32
    const float* weight = (const float*)d_in[1];   // [512, 512]   f32
    const void*  edges  = d_in[2];                 // [2, E] int64 or int32
    float* out = (float*)d_out;
    const int E = out_size;

    // 1. W^T hi/lo split + edge dtype detect
    wt_convert_kernel<<<dim3(16, 16), dim3(32, 8)>>>(weight,
                                                     (const unsigned int*)edges);
    // 2. ZW = Z @ W (split-bf16 MMA)
    gemm_kernel<<<dim3(NDIM / 128, (MDIM + 127) / 128), 256>>>(z_drug);

    // 3. per-edge scores
    edge_kernel<<<(E + 7) / 8, 256>>>(z_drug, edges, out, E);
}